// round 1
// baseline (speedup 1.0000x reference)
#include <cuda_runtime.h>
#include <cuda_bf16.h>
#include <math.h>

#define Bn    8
#define Hn    384
#define Wn    384
#define HW    (Hn*Wn)
#define NPIX  (Bn*HW)
#define NCLS  4
#define EDIM  8
#define NINST 33
#define RUNS_PER_IMG (HW/16)
#define RUNS_X       (Wn/16)

// ---------------- scratch (device globals; no allocation allowed) -------------
__device__ double g_sem, g_a9, g_a3, g_a4;
__device__ float  g_cnt [Bn*NINST];
__device__ float  g_ws  [Bn*NINST];
__device__ float  g_ew  [Bn*NINST*EDIM];
__device__ float  g_pull[Bn*NINST];
__device__ float  g_ctr [Bn*NINST*EDIM];

__global__ void k_zero() {
    int t = threadIdx.x;
    if (t == 0) { g_sem = 0.0; g_a9 = 0.0; g_a3 = 0.0; g_a4 = 0.0; }
    for (int i = t; i < Bn*NINST; i += blockDim.x) { g_cnt[i]=0.f; g_ws[i]=0.f; g_pull[i]=0.f; }
    for (int i = t; i < Bn*NINST*EDIM; i += blockDim.x) g_ew[i]=0.f;
}

__device__ __forceinline__ double warp_red(double v){
    #pragma unroll
    for (int o = 16; o > 0; o >>= 1) v += __shfl_down_sync(0xffffffffu, v, o);
    return v;
}

// ---------------- K1: semantic NLL + affinity L1 (streaming reduction) --------
__global__ void k_semaff(const float* __restrict__ sem, const int* __restrict__ cl,
                         const float* __restrict__ geo, const float* __restrict__ gd,
                         const float* __restrict__ gg,  const float* __restrict__ gr)
{
    double s = 0, a9 = 0, a3 = 0, a4 = 0;
    int stride = gridDim.x * blockDim.x;
    for (int p = blockIdx.x*blockDim.x + threadIdx.x; p < NPIX; p += stride) {
        int b = p / HW;
        int q = p - b*HW;

        size_t sb = (size_t)b*NCLS*HW + q;
        float x0 = sem[sb], x1 = sem[sb+HW], x2 = sem[sb+2*(size_t)HW], x3 = sem[sb+3*(size_t)HW];
        float m = fmaxf(fmaxf(x0,x1), fmaxf(x2,x3));
        float lse = m + logf(expf(x0-m)+expf(x1-m)+expf(x2-m)+expf(x3-m));
        int c = cl[p];
        float xc = (c==0) ? x0 : ((c==1) ? x1 : ((c==2) ? x2 : x3));
        s += (double)(lse - xc);

        const float* gp  = geo + (size_t)b*16*HW + q;
        const float* dp  = gd  + (size_t)b*9 *HW + q;
        const float* gg2 = gg  + (size_t)b*3 *HW + q;
        const float* rp  = gr  + (size_t)b*4 *HW + q;
        float t9 = 0, t3 = 0, t4 = 0;
        #pragma unroll
        for (int i = 0; i < 9; i++) t9 += fabsf(gp[(size_t)i*HW]      - dp[(size_t)i*HW]);
        #pragma unroll
        for (int i = 0; i < 3; i++) t3 += fabsf(gp[(size_t)(9+i)*HW]  - gg2[(size_t)i*HW]);
        #pragma unroll
        for (int i = 0; i < 4; i++) t4 += fabsf(gp[(size_t)(12+i)*HW] - rp[(size_t)i*HW]);
        a9 += (double)t9; a3 += (double)t3; a4 += (double)t4;
    }

    __shared__ double sh[4][8];
    int lane = threadIdx.x & 31, wid = threadIdx.x >> 5;
    s = warp_red(s); a9 = warp_red(a9); a3 = warp_red(a3); a4 = warp_red(a4);
    if (lane == 0) { sh[0][wid]=s; sh[1][wid]=a9; sh[2][wid]=a3; sh[3][wid]=a4; }
    __syncthreads();
    if (wid == 0) {
        int nw = blockDim.x >> 5;
        double v0 = lane < nw ? sh[0][lane] : 0.0;
        double v1 = lane < nw ? sh[1][lane] : 0.0;
        double v2 = lane < nw ? sh[2][lane] : 0.0;
        double v3 = lane < nw ? sh[3][lane] : 0.0;
        v0 = warp_red(v0); v1 = warp_red(v1); v2 = warp_red(v2); v3 = warp_red(v3);
        if (lane == 0) {
            atomicAdd(&g_sem, v0); atomicAdd(&g_a9, v1);
            atomicAdd(&g_a3, v2);  atomicAdd(&g_a4, v3);
        }
    }
}

// ---------------- boundary weight: 3x3 morphological gradient, replicate pad --
__device__ __forceinline__ float bweight(const int* __restrict__ L, int y, int x, int l)
{
    int ym = y > 0 ? y-1 : 0, yp = y < Hn-1 ? y+1 : Hn-1;
    int xm = x > 0 ? x-1 : 0, xp = x < Wn-1 ? x+1 : Wn-1;
    const int* r0 = L + ym*Wn;
    const int* r1 = L + y *Wn;
    const int* r2 = L + yp*Wn;
    bool bd = (r0[xm]!=l) | (r0[x]!=l) | (r0[xp]!=l)
            | (r1[xm]!=l) |              (r1[xp]!=l)
            | (r2[xm]!=l) | (r2[x]!=l) | (r2[xp]!=l);
    return bd ? 10.0f : 1.0f;
}

// ---------------- K2: segment sums cnt / w_sum / weighted-embed sum -----------
__global__ void k_seg(const int* __restrict__ lbl, const float* __restrict__ emb)
{
    int b = blockIdx.y;
    __shared__ float s_cnt[NINST], s_ws[NINST], s_ew[NINST*EDIM];
    for (int i = threadIdx.x; i < NINST; i += blockDim.x) { s_cnt[i]=0.f; s_ws[i]=0.f; }
    for (int i = threadIdx.x; i < NINST*EDIM; i += blockDim.x) s_ew[i]=0.f;
    __syncthreads();

    const int*   L = lbl + b*HW;
    const float* E = emb + (size_t)b*EDIM*HW;

    for (int r = blockIdx.x*blockDim.x + threadIdx.x; r < RUNS_PER_IMG; r += gridDim.x*blockDim.x) {
        int y  = r / RUNS_X;
        int x0 = (r - y*RUNS_X) * 16;
        int base = y*Wn + x0;

        int ls[16];
        const int4* Lp = (const int4*)(L + base);
        #pragma unroll
        for (int i = 0; i < 4; i++) {
            int4 v = Lp[i];
            ls[4*i]=v.x; ls[4*i+1]=v.y; ls[4*i+2]=v.z; ls[4*i+3]=v.w;
        }
        bool uni = true;
        #pragma unroll
        for (int i = 1; i < 16; i++) uni &= (ls[i] == ls[0]);

        float wv[16];
        #pragma unroll
        for (int i = 0; i < 16; i++) wv[i] = bweight(L, y, x0+i, ls[i]);

        if (uni) {  // fast path (labels are 16-aligned blocky)
            int l = ls[0];
            float wsum = 0;
            #pragma unroll
            for (int i = 0; i < 16; i++) wsum += wv[i];
            atomicAdd(&s_cnt[l], 16.0f);
            atomicAdd(&s_ws [l], wsum);
            #pragma unroll
            for (int c = 0; c < EDIM; c++) {
                const float4* Ep = (const float4*)(E + (size_t)c*HW + base);
                float acc = 0;
                #pragma unroll
                for (int i = 0; i < 4; i++) {
                    float4 e = Ep[i];
                    acc += e.x*wv[4*i] + e.y*wv[4*i+1] + e.z*wv[4*i+2] + e.w*wv[4*i+3];
                }
                atomicAdd(&s_ew[l*EDIM+c], acc);
            }
        } else {    // generic fallback
            #pragma unroll 1
            for (int i = 0; i < 16; i++) {
                int l = ls[i];
                atomicAdd(&s_cnt[l], 1.0f);
                atomicAdd(&s_ws [l], wv[i]);
                for (int c = 0; c < EDIM; c++)
                    atomicAdd(&s_ew[l*EDIM+c], E[(size_t)c*HW + base + i] * wv[i]);
            }
        }
    }
    __syncthreads();
    for (int i = threadIdx.x; i < NINST; i += blockDim.x) {
        if (s_cnt[i] != 0.f) atomicAdd(&g_cnt[b*NINST+i], s_cnt[i]);
        if (s_ws [i] != 0.f) atomicAdd(&g_ws [b*NINST+i], s_ws [i]);
    }
    for (int i = threadIdx.x; i < NINST*EDIM; i += blockDim.x)
        if (s_ew[i] != 0.f) atomicAdd(&g_ew[b*NINST*EDIM+i], s_ew[i]);
}

// ---------------- K2b: centers = ew / (w_sum + eps) ---------------------------
__global__ void k_ctr()
{
    int i = blockIdx.x*blockDim.x + threadIdx.x;
    if (i < Bn*NINST) {
        float inv = 1.0f / (g_ws[i] + 1e-8f);
        #pragma unroll
        for (int c = 0; c < EDIM; c++) g_ctr[i*EDIM+c] = g_ew[i*EDIM+c] * inv;
    }
}

// ---------------- K3: pull term (second pass over embeddings) -----------------
__global__ void k_pull(const int* __restrict__ lbl, const float* __restrict__ emb)
{
    int b = blockIdx.y;
    __shared__ float s_pull[NINST];
    for (int i = threadIdx.x; i < NINST; i += blockDim.x) s_pull[i] = 0.f;
    __syncthreads();

    const int*   L = lbl + b*HW;
    const float* E = emb + (size_t)b*EDIM*HW;
    const float* C = g_ctr + b*NINST*EDIM;

    for (int r = blockIdx.x*blockDim.x + threadIdx.x; r < RUNS_PER_IMG; r += gridDim.x*blockDim.x) {
        int y  = r / RUNS_X;
        int x0 = (r - y*RUNS_X) * 16;
        int base = y*Wn + x0;

        int ls[16];
        const int4* Lp = (const int4*)(L + base);
        #pragma unroll
        for (int i = 0; i < 4; i++) {
            int4 v = Lp[i];
            ls[4*i]=v.x; ls[4*i+1]=v.y; ls[4*i+2]=v.z; ls[4*i+3]=v.w;
        }
        bool uni = true;
        #pragma unroll
        for (int i = 1; i < 16; i++) uni &= (ls[i] == ls[0]);

        float wv[16];
        #pragma unroll
        for (int i = 0; i < 16; i++) wv[i] = bweight(L, y, x0+i, ls[i]);

        if (uni) {
            int l = ls[0];
            float ss[16];
            #pragma unroll
            for (int i = 0; i < 16; i++) ss[i] = 0.f;
            #pragma unroll
            for (int c = 0; c < EDIM; c++) {
                float cc = C[l*EDIM+c];
                const float4* Ep = (const float4*)(E + (size_t)c*HW + base);
                #pragma unroll
                for (int i = 0; i < 4; i++) {
                    float4 e = Ep[i];
                    float d0=e.x-cc, d1=e.y-cc, d2=e.z-cc, d3=e.w-cc;
                    ss[4*i]+=d0*d0; ss[4*i+1]+=d1*d1; ss[4*i+2]+=d2*d2; ss[4*i+3]+=d3*d3;
                }
            }
            float acc = 0;
            #pragma unroll
            for (int i = 0; i < 16; i++) {
                float dist = sqrtf(fmaxf(ss[i], 1e-12f));
                float t = fmaxf(dist - 0.5f, 0.f);
                acc += t*t*wv[i];
            }
            atomicAdd(&s_pull[l], acc);
        } else {
            #pragma unroll 1
            for (int i = 0; i < 16; i++) {
                int l = ls[i];
                float ssv = 0;
                for (int c = 0; c < EDIM; c++) {
                    float d = E[(size_t)c*HW + base + i] - C[l*EDIM+c];
                    ssv += d*d;
                }
                float dist = sqrtf(fmaxf(ssv, 1e-12f));
                float t = fmaxf(dist - 0.5f, 0.f);
                atomicAdd(&s_pull[l], t*t*wv[i]);
            }
        }
    }
    __syncthreads();
    for (int i = threadIdx.x; i < NINST; i += blockDim.x)
        if (s_pull[i] != 0.f) atomicAdd(&g_pull[b*NINST+i], s_pull[i]);
}

// ---------------- K4: finalize (push pairs, norm, combine) --------------------
__global__ void k_fin(float* __restrict__ out, int out_size)
{
    __shared__ float sp[Bn], sq[Bn], sn[Bn];
    __shared__ int   spres[Bn];
    int b = threadIdx.x;
    if (b < Bn) {
        float pull = 0, norm = 0; int np = 0;
        bool pres[NINST];
        for (int k = 0; k < NINST; k++) {
            pres[k] = (k > 0) && (g_cnt[b*NINST+k] > 0.f);
            if (pres[k]) {
                pull += g_pull[b*NINST+k] / fmaxf(g_cnt[b*NINST+k], 1.0f);
                float ssn = 0;
                for (int c = 0; c < EDIM; c++) { float v = g_ctr[(b*NINST+k)*EDIM+c]; ssn += v*v; }
                norm += sqrtf(fmaxf(ssn, 1e-12f));
                np++;
            }
        }
        float push = 0; int npair = 0;
        for (int i = 0; i < NINST; i++) if (pres[i])
            for (int j = i+1; j < NINST; j++) if (pres[j]) {
                float ssd = 0;
                for (int c = 0; c < EDIM; c++) {
                    float d = g_ctr[(b*NINST+i)*EDIM+c] - g_ctr[(b*NINST+j)*EDIM+c];
                    ssd += d*d;
                }
                float pd = sqrtf(fmaxf(ssd, 1e-12f));
                float t = fmaxf(2.0f*1.5f - pd, 0.f);
                push += t*t; npair++;
            }
        sp[b] = pull;
        sq[b] = push / fmaxf((float)npair, 1.0f);
        sn[b] = norm / fmaxf((float)np, 1.0f);
        spres[b] = (np > 0) ? 1 : 0;
    }
    __syncthreads();
    if (threadIdx.x == 0) {
        float pull = 0, push = 0, norm = 0; int n = 0;
        for (int bb = 0; bb < Bn; bb++) { pull += sp[bb]; push += sq[bb]; norm += sn[bb]; n += spres[bb]; }
        float nn  = fmaxf((float)n, 1.0f);
        float ins = (1.0f*pull + 1.0f*push + 0.001f*norm) / nn;
        float semv = (float)(g_sem / (double)NPIX);
        float aff  = (float)(g_a9/(double)((size_t)Bn*9*HW)
                           + g_a3/(double)((size_t)Bn*3*HW)
                           + g_a4/(double)((size_t)Bn*4*HW));
        float total = semv + aff + ins;
        out[0] = total;
        if (out_size > 1) out[1] = semv;
        if (out_size > 2) out[2] = aff;
        if (out_size > 3) out[3] = ins;
    }
}

// ---------------- entry -------------------------------------------------------
extern "C" void kernel_launch(void* const* d_in, const int* in_sizes, int n_in,
                              void* d_out, int out_size)
{
    const float* sem  = (const float*)d_in[0];
    const int*   cl   = (const int*)  d_in[1];
    const float* inst = (const float*)d_in[2];
    const float* geo  = (const float*)d_in[3];
    const float* gd   = (const float*)d_in[4];
    const float* gg   = (const float*)d_in[5];
    const float* gr   = (const float*)d_in[6];
    const int*   lbl  = (const int*)  d_in[7];
    float* out = (float*)d_out;

    k_zero<<<1, 256>>>();
    k_semaff<<<2368, 256>>>(sem, cl, geo, gd, gg, gr);
    dim3 g2(36, Bn);
    k_seg<<<g2, 256>>>(lbl, inst);
    k_ctr<<<1, 288>>>();
    k_pull<<<g2, 256>>>(lbl, inst);
    k_fin<<<1, 32>>>(out, out_size);
}

// round 2
// speedup vs baseline: 2.4991x; 2.4991x over previous
#include <cuda_runtime.h>
#include <cuda_bf16.h>
#include <math.h>

#define Bn    8
#define Hn    384
#define Wn    384
#define HW    (Hn*Wn)
#define NPIX  (Bn*HW)
#define NCLS  4
#define EDIM  8
#define NINST 33
#define RUNS_PER_IMG (HW/16)          // 9216
#define RUNS_X       (Wn/16)          // 24
#define SEM_BLOCKS   (NPIX/4/256)     // 1152 blocks, 4 pixels/thread
#define SEG_BLK_PER_IMG 36            // 36*256 = 9216 runs, 1 run/thread
#define SEG_BLOCKS   (SEG_BLK_PER_IMG*Bn)

// ---------------- scratch (single struct -> one memset node) -----------------
struct Scr {
    double sem, a9, a3, a4;
    float  cnt [Bn*NINST];
    float  ws  [Bn*NINST];
    float  ew  [Bn*NINST*EDIM];
    float  pull[Bn*NINST];
};
__device__ Scr g_s;

__device__ __forceinline__ double warp_redd(double v){
    #pragma unroll
    for (int o = 16; o > 0; o >>= 1) v += __shfl_down_sync(0xffffffffu, v, o);
    return v;
}
__device__ __forceinline__ float warp_redf(float v){
    #pragma unroll
    for (int o = 16; o > 0; o >>= 1) v += __shfl_down_sync(0xffffffffu, v, o);
    return v;
}

// Load the 3 label rows (18 cols, replicate-padded) around a 16-run into registers.
__device__ __forceinline__ void load_rows(const int* __restrict__ L, int y, int x0,
                                          int te[18], int me[18], int be[18])
{
    int ym = y > 0 ? y-1 : 0, yp = y < Hn-1 ? y+1 : Hn-1;
    int xl = x0 > 0 ? x0-1 : 0;
    int xr = x0+16 < Wn ? x0+16 : Wn-1;
    const int* rT = L + ym*Wn;
    const int* rM = L + y *Wn;
    const int* rB = L + yp*Wn;
    const int4* t4 = (const int4*)(rT + x0);
    const int4* m4 = (const int4*)(rM + x0);
    const int4* b4 = (const int4*)(rB + x0);
    #pragma unroll
    for (int i = 0; i < 4; i++) {
        int4 a = t4[i]; te[1+4*i]=a.x; te[2+4*i]=a.y; te[3+4*i]=a.z; te[4+4*i]=a.w;
        int4 b = m4[i]; me[1+4*i]=b.x; me[2+4*i]=b.y; me[3+4*i]=b.z; me[4+4*i]=b.w;
        int4 c = b4[i]; be[1+4*i]=c.x; be[2+4*i]=c.y; be[3+4*i]=c.z; be[4+4*i]=c.w;
    }
    te[0]=rT[xl]; te[17]=rT[xr];
    me[0]=rM[xl]; me[17]=rM[xr];
    be[0]=rB[xl]; be[17]=rB[xr];
}

__device__ __forceinline__ void calc_w(const int te[18], const int me[18], const int be[18],
                                       float wv[16])
{
    #pragma unroll
    for (int i = 0; i < 16; i++) {
        int l = me[i+1];
        bool bd = (te[i]!=l) | (te[i+1]!=l) | (te[i+2]!=l)
                | (me[i]!=l) |                (me[i+2]!=l)
                | (be[i]!=l) | (be[i+1]!=l) | (be[i+2]!=l);
        wv[i] = bd ? 10.0f : 1.0f;
    }
}

// ======== K1: fused (semantic NLL + affinity L1) || (segment sums) ============
__global__ void __launch_bounds__(256)
K1(const float* __restrict__ sem, const int* __restrict__ cl,
   const float* __restrict__ geo, const float* __restrict__ gd,
   const float* __restrict__ gg,  const float* __restrict__ gr,
   const int*   __restrict__ lbl, const float* __restrict__ emb)
{
    if (blockIdx.x < SEM_BLOCKS) {
        // ---------------- semantic + affinity, float4 (4 px / thread) --------
        int t  = blockIdx.x*blockDim.x + threadIdx.x;          // group id
        int H4 = HW/4;
        int b  = t / H4;
        int q4 = t - b*H4;
        size_t q = (size_t)q4 * 4;

        // semantic logits for 4 pixels
        const float4* s4 = (const float4*)(sem + (size_t)b*NCLS*HW + q);
        float4 x0 = s4[0];
        float4 x1 = s4[HW/4];
        float4 x2 = s4[2*(HW/4)];
        float4 x3 = s4[3*(HW/4)];
        int4 cc = *(const int4*)(cl + (size_t)b*HW + q);

        double s = 0.0;
        {
            float a[4][4] = {{x0.x,x1.x,x2.x,x3.x},{x0.y,x1.y,x2.y,x3.y},
                             {x0.z,x1.z,x2.z,x3.z},{x0.w,x1.w,x2.w,x3.w}};
            int   ci[4] = {cc.x, cc.y, cc.z, cc.w};
            #pragma unroll
            for (int j = 0; j < 4; j++) {
                float m = fmaxf(fmaxf(a[j][0],a[j][1]), fmaxf(a[j][2],a[j][3]));
                float sum = __expf(a[j][0]-m)+__expf(a[j][1]-m)
                          + __expf(a[j][2]-m)+__expf(a[j][3]-m);
                float lse = m + __logf(sum);
                int c = ci[j];
                float xc = (c==0) ? a[j][0] : ((c==1) ? a[j][1] : ((c==2) ? a[j][2] : a[j][3]));
                s += (double)(lse - xc);
            }
        }

        // affinity L1 (float4 per channel)
        const float4* gp = (const float4*)(geo + (size_t)b*16*HW + q);
        const float4* dp = (const float4*)(gd  + (size_t)b*9 *HW + q);
        const float4* gp2= (const float4*)(gg  + (size_t)b*3 *HW + q);
        const float4* rp = (const float4*)(gr  + (size_t)b*4 *HW + q);
        float t9 = 0, t3 = 0, t4v = 0;
        #pragma unroll
        for (int i = 0; i < 9; i++) {
            float4 a = gp[(size_t)i*(HW/4)], c = dp[(size_t)i*(HW/4)];
            t9 += fabsf(a.x-c.x)+fabsf(a.y-c.y)+fabsf(a.z-c.z)+fabsf(a.w-c.w);
        }
        #pragma unroll
        for (int i = 0; i < 3; i++) {
            float4 a = gp[(size_t)(9+i)*(HW/4)], c = gp2[(size_t)i*(HW/4)];
            t3 += fabsf(a.x-c.x)+fabsf(a.y-c.y)+fabsf(a.z-c.z)+fabsf(a.w-c.w);
        }
        #pragma unroll
        for (int i = 0; i < 4; i++) {
            float4 a = gp[(size_t)(12+i)*(HW/4)], c = rp[(size_t)i*(HW/4)];
            t4v += fabsf(a.x-c.x)+fabsf(a.y-c.y)+fabsf(a.z-c.z)+fabsf(a.w-c.w);
        }

        // block reduce (doubles)
        __shared__ double sh[4][8];
        int lane = threadIdx.x & 31, wid = threadIdx.x >> 5;
        double v0 = warp_redd(s);
        double v1 = warp_redd((double)t9);
        double v2 = warp_redd((double)t3);
        double v3 = warp_redd((double)t4v);
        if (lane == 0) { sh[0][wid]=v0; sh[1][wid]=v1; sh[2][wid]=v2; sh[3][wid]=v3; }
        __syncthreads();
        if (wid == 0) {
            v0 = lane < 8 ? sh[0][lane] : 0.0;
            v1 = lane < 8 ? sh[1][lane] : 0.0;
            v2 = lane < 8 ? sh[2][lane] : 0.0;
            v3 = lane < 8 ? sh[3][lane] : 0.0;
            v0 = warp_redd(v0); v1 = warp_redd(v1); v2 = warp_redd(v2); v3 = warp_redd(v3);
            if (lane == 0) {
                atomicAdd(&g_s.sem, v0); atomicAdd(&g_s.a9, v1);
                atomicAdd(&g_s.a3, v2);  atomicAdd(&g_s.a4, v3);
            }
        }
    } else {
        // ---------------- segment sums: cnt / w_sum / weighted-embed sum -----
        int bid = blockIdx.x - SEM_BLOCKS;
        int b   = bid / SEG_BLK_PER_IMG;
        int blk = bid - b*SEG_BLK_PER_IMG;

        __shared__ float s_cnt[NINST], s_ws[NINST], s_ew[NINST*EDIM];
        for (int i = threadIdx.x; i < NINST; i += blockDim.x) { s_cnt[i]=0.f; s_ws[i]=0.f; }
        for (int i = threadIdx.x; i < NINST*EDIM; i += blockDim.x) s_ew[i]=0.f;
        __syncthreads();

        const int*   L = lbl + b*HW;
        const float* E = emb + (size_t)b*EDIM*HW;

        int r = blk*blockDim.x + threadIdx.x;        // exactly one run per thread
        int y  = r / RUNS_X;
        int x0 = (r - y*RUNS_X) * 16;
        int base = y*Wn + x0;

        int te[18], me[18], be[18];
        load_rows(L, y, x0, te, me, be);
        float wv[16];
        calc_w(te, me, be, wv);

        bool uni = true;
        #pragma unroll
        for (int i = 1; i < 16; i++) uni &= (me[i+1] == me[1]);

        if (uni) {
            int l = me[1];
            float wsum = 0;
            #pragma unroll
            for (int i = 0; i < 16; i++) wsum += wv[i];
            atomicAdd(&s_cnt[l], 16.0f);
            atomicAdd(&s_ws [l], wsum);
            #pragma unroll
            for (int c = 0; c < EDIM; c++) {
                const float4* Ep = (const float4*)(E + (size_t)c*HW + base);
                float acc = 0;
                #pragma unroll
                for (int i = 0; i < 4; i++) {
                    float4 e = Ep[i];
                    acc += e.x*wv[4*i] + e.y*wv[4*i+1] + e.z*wv[4*i+2] + e.w*wv[4*i+3];
                }
                atomicAdd(&s_ew[l*EDIM+c], acc);
            }
        } else {
            #pragma unroll 1
            for (int i = 0; i < 16; i++) {
                int l = me[i+1];
                atomicAdd(&s_cnt[l], 1.0f);
                atomicAdd(&s_ws [l], wv[i]);
                for (int c = 0; c < EDIM; c++)
                    atomicAdd(&s_ew[l*EDIM+c], E[(size_t)c*HW + base + i] * wv[i]);
            }
        }
        __syncthreads();
        for (int i = threadIdx.x; i < NINST; i += blockDim.x) {
            if (s_cnt[i] != 0.f) atomicAdd(&g_s.cnt[b*NINST+i], s_cnt[i]);
            if (s_ws [i] != 0.f) atomicAdd(&g_s.ws [b*NINST+i], s_ws [i]);
        }
        for (int i = threadIdx.x; i < NINST*EDIM; i += blockDim.x)
            if (s_ew[i] != 0.f) atomicAdd(&g_s.ew[b*NINST*EDIM+i], s_ew[i]);
    }
}

// ======== K2: pull term (centers recomputed per block into shared) ============
__global__ void __launch_bounds__(256)
K2(const int* __restrict__ lbl, const float* __restrict__ emb)
{
    int b = blockIdx.y;
    __shared__ float s_ctr[NINST*EDIM];
    __shared__ float s_pull[NINST];
    for (int i = threadIdx.x; i < NINST*EDIM; i += blockDim.x)
        s_ctr[i] = g_s.ew[b*NINST*EDIM + i] / (g_s.ws[b*NINST + (i>>3)] + 1e-8f);
    for (int i = threadIdx.x; i < NINST; i += blockDim.x) s_pull[i] = 0.f;
    __syncthreads();

    const int*   L = lbl + b*HW;
    const float* E = emb + (size_t)b*EDIM*HW;

    int r = blockIdx.x*blockDim.x + threadIdx.x;
    int y  = r / RUNS_X;
    int x0 = (r - y*RUNS_X) * 16;
    int base = y*Wn + x0;

    int te[18], me[18], be[18];
    load_rows(L, y, x0, te, me, be);
    float wv[16];
    calc_w(te, me, be, wv);

    bool uni = true;
    #pragma unroll
    for (int i = 1; i < 16; i++) uni &= (me[i+1] == me[1]);

    if (uni) {
        int l = me[1];
        float ss[16];
        #pragma unroll
        for (int i = 0; i < 16; i++) ss[i] = 0.f;
        #pragma unroll
        for (int c = 0; c < EDIM; c++) {
            float cc = s_ctr[l*EDIM+c];
            const float4* Ep = (const float4*)(E + (size_t)c*HW + base);
            #pragma unroll
            for (int i = 0; i < 4; i++) {
                float4 e = Ep[i];
                float d0=e.x-cc, d1=e.y-cc, d2=e.z-cc, d3=e.w-cc;
                ss[4*i]+=d0*d0; ss[4*i+1]+=d1*d1; ss[4*i+2]+=d2*d2; ss[4*i+3]+=d3*d3;
            }
        }
        float acc = 0;
        #pragma unroll
        for (int i = 0; i < 16; i++) {
            float dist = sqrtf(fmaxf(ss[i], 1e-12f));
            float t = fmaxf(dist - 0.5f, 0.f);
            acc += t*t*wv[i];
        }
        atomicAdd(&s_pull[l], acc);
    } else {
        #pragma unroll 1
        for (int i = 0; i < 16; i++) {
            int l = me[i+1];
            float ssv = 0;
            for (int c = 0; c < EDIM; c++) {
                float d = E[(size_t)c*HW + base + i] - s_ctr[l*EDIM+c];
                ssv += d*d;
            }
            float dist = sqrtf(fmaxf(ssv, 1e-12f));
            float t = fmaxf(dist - 0.5f, 0.f);
            atomicAdd(&s_pull[l], t*t*wv[i]);
        }
    }
    __syncthreads();
    for (int i = threadIdx.x; i < NINST; i += blockDim.x)
        if (s_pull[i] != 0.f) atomicAdd(&g_s.pull[b*NINST+i], s_pull[i]);
}

// ======== K3: finalize (push pairs, norm, combine) ============================
__global__ void __launch_bounds__(256)
K3(float* __restrict__ out, int out_size)
{
    __shared__ float s_ctr[Bn][NINST*EDIM];
    __shared__ float s_cnt[Bn][NINST];
    __shared__ float rp[Bn], rq[Bn], rn[Bn];
    __shared__ int   rpres[Bn];

    for (int i = threadIdx.x; i < Bn*NINST*EDIM; i += blockDim.x) {
        int b = i / (NINST*EDIM), k = i % (NINST*EDIM);
        s_ctr[b][k] = g_s.ew[i] / (g_s.ws[b*NINST + (k>>3)] + 1e-8f);
    }
    for (int i = threadIdx.x; i < Bn*NINST; i += blockDim.x)
        s_cnt[i/NINST][i%NINST] = g_s.cnt[i];
    __syncthreads();

    int wid = threadIdx.x >> 5, lane = threadIdx.x & 31;
    if (wid < Bn) {
        int b = wid;
        float pull = 0, norm = 0; int np = 0;
        for (int k = lane; k < NINST; k += 32) {
            bool pres = (k > 0) && (s_cnt[b][k] > 0.f);
            if (pres) {
                pull += g_s.pull[b*NINST+k] / fmaxf(s_cnt[b][k], 1.0f);
                float ssn = 0;
                #pragma unroll
                for (int c = 0; c < EDIM; c++) { float v = s_ctr[b][k*EDIM+c]; ssn += v*v; }
                norm += sqrtf(fmaxf(ssn, 1e-12f));
                np++;
            }
        }
        float push = 0; int npair = 0;
        for (int idx = lane; idx < NINST*NINST; idx += 32) {
            int i = idx / NINST, j = idx % NINST;
            if (j > i && i > 0 && s_cnt[b][i] > 0.f && s_cnt[b][j] > 0.f) {
                float ssd = 0;
                #pragma unroll
                for (int c = 0; c < EDIM; c++) {
                    float d = s_ctr[b][i*EDIM+c] - s_ctr[b][j*EDIM+c];
                    ssd += d*d;
                }
                float pd = sqrtf(fmaxf(ssd, 1e-12f));
                float t = fmaxf(3.0f - pd, 0.f);
                push += t*t; npair++;
            }
        }
        pull = warp_redf(pull); norm = warp_redf(norm); push = warp_redf(push);
        np   = __reduce_add_sync(0xffffffffu, np);
        npair= __reduce_add_sync(0xffffffffu, npair);
        if (lane == 0) {
            rp[b] = pull;
            rq[b] = push / fmaxf((float)npair, 1.0f);
            rn[b] = (norm / fmaxf((float)np, 1.0f));
            rpres[b] = (np > 0) ? 1 : 0;
        }
    }
    __syncthreads();
    if (threadIdx.x == 0) {
        float pull = 0, push = 0, norm = 0; int n = 0;
        for (int bb = 0; bb < Bn; bb++) { pull += rp[bb]; push += rq[bb]; norm += rn[bb]; n += rpres[bb]; }
        float nn  = fmaxf((float)n, 1.0f);
        float ins = (pull + push + 0.001f*norm) / nn;
        float semv = (float)(g_s.sem / (double)NPIX);
        float aff  = (float)(g_s.a9/(double)((size_t)Bn*9*HW)
                           + g_s.a3/(double)((size_t)Bn*3*HW)
                           + g_s.a4/(double)((size_t)Bn*4*HW));
        float total = semv + aff + ins;
        out[0] = total;
        if (out_size > 1) out[1] = semv;
        if (out_size > 2) out[2] = aff;
        if (out_size > 3) out[3] = ins;
    }
}

// ---------------- entry -------------------------------------------------------
extern "C" void kernel_launch(void* const* d_in, const int* in_sizes, int n_in,
                              void* d_out, int out_size)
{
    const float* sem  = (const float*)d_in[0];
    const int*   cl   = (const int*)  d_in[1];
    const float* inst = (const float*)d_in[2];
    const float* geo  = (const float*)d_in[3];
    const float* gd   = (const float*)d_in[4];
    const float* gg   = (const float*)d_in[5];
    const float* gr   = (const float*)d_in[6];
    const int*   lbl  = (const int*)  d_in[7];
    float* out = (float*)d_out;

    void* scr = nullptr;
    cudaGetSymbolAddress(&scr, g_s);
    cudaMemsetAsync(scr, 0, sizeof(Scr));

    K1<<<SEM_BLOCKS + SEG_BLOCKS, 256>>>(sem, cl, geo, gd, gg, gr, lbl, inst);
    dim3 g2(SEG_BLK_PER_IMG, Bn);
    K2<<<g2, 256>>>(lbl, inst);
    K3<<<1, 256>>>(out, out_size);
}

// round 3
// speedup vs baseline: 3.1268x; 1.2512x over previous
#include <cuda_runtime.h>
#include <cuda_bf16.h>
#include <math.h>

#define Bn    8
#define Hn    384
#define Wn    384
#define HW    (Hn*Wn)
#define NPIX  (Bn*HW)
#define NCLS  4
#define EDIM  8
#define NINST 33
#define RUNS_PER_IMG (HW/16)          // 9216
#define RUNS_X       (Wn/16)          // 24
#define SEM_BLOCKS   (NPIX/4/256)     // 1152
#define SEG_BLK_PER_IMG 36            // 36*256 = 9216 runs/img
#define SEG_BLOCKS   (SEG_BLK_PER_IMG*Bn)      // 288
#define HR_PER_IMG   (RUNS_PER_IMG*2)          // 18432 half-runs (8px)
#define K2_BLK_PER_IMG (HR_PER_IMG/256)        // 72
#define K2_BLOCKS    (K2_BLK_PER_IMG*Bn)       // 576

// ---------------- scratch ----------------------------------------------------
struct Scr {
    double sem, a9, a3, a4;
    float  cnt [Bn*NINST];
    float  ws  [Bn*NINST];
    float  ew  [Bn*NINST*EDIM];
    float  pull[Bn*NINST];
};
__device__ Scr g_s;
__device__ unsigned int g_runinfo[Bn*RUNS_PER_IMG];   // mask16 | label<<16 | uni<<31

__device__ __forceinline__ double warp_redd(double v){
    #pragma unroll
    for (int o = 16; o > 0; o >>= 1) v += __shfl_down_sync(0xffffffffu, v, o);
    return v;
}
__device__ __forceinline__ float warp_redf(float v){
    #pragma unroll
    for (int o = 16; o > 0; o >>= 1) v += __shfl_down_sync(0xffffffffu, v, o);
    return v;
}

// per-pixel boundary weight (fallback only)
__device__ __forceinline__ float bweight(const int* __restrict__ L, int y, int x, int l)
{
    int ym = y > 0 ? y-1 : 0, yp = y < Hn-1 ? y+1 : Hn-1;
    int xm = x > 0 ? x-1 : 0, xp = x < Wn-1 ? x+1 : Wn-1;
    const int* r0 = L + ym*Wn;
    const int* r1 = L + y *Wn;
    const int* r2 = L + yp*Wn;
    bool bd = (r0[xm]!=l) | (r0[x]!=l) | (r0[xp]!=l)
            | (r1[xm]!=l) |              (r1[xp]!=l)
            | (r2[xm]!=l) | (r2[x]!=l) | (r2[xp]!=l);
    return bd ? 10.0f : 1.0f;
}

// ======== K1: fused (semantic NLL + affinity L1) || (segment sums) ============
__global__ void __launch_bounds__(256, 5)
K1(const float* __restrict__ sem, const int* __restrict__ cl,
   const float* __restrict__ geo, const float* __restrict__ gd,
   const float* __restrict__ gg,  const float* __restrict__ gr,
   const int*   __restrict__ lbl, const float* __restrict__ emb)
{
    if (blockIdx.x < SEM_BLOCKS) {
        // ---------------- semantic + affinity, float4 (4 px / thread) --------
        int t  = blockIdx.x*blockDim.x + threadIdx.x;
        int H4 = HW/4;
        int b  = t / H4;
        int q4 = t - b*H4;
        size_t q = (size_t)q4 * 4;

        const float4* s4 = (const float4*)(sem + (size_t)b*NCLS*HW + q);
        float4 x0 = __ldcs(s4);
        float4 x1 = __ldcs(s4 + HW/4);
        float4 x2 = __ldcs(s4 + 2*(HW/4));
        float4 x3 = __ldcs(s4 + 3*(HW/4));
        int4 cc = __ldcs((const int4*)(cl + (size_t)b*HW + q));

        float s = 0.f;
        {
            float a[4][4] = {{x0.x,x1.x,x2.x,x3.x},{x0.y,x1.y,x2.y,x3.y},
                             {x0.z,x1.z,x2.z,x3.z},{x0.w,x1.w,x2.w,x3.w}};
            int   ci[4] = {cc.x, cc.y, cc.z, cc.w};
            #pragma unroll
            for (int j = 0; j < 4; j++) {
                float m = fmaxf(fmaxf(a[j][0],a[j][1]), fmaxf(a[j][2],a[j][3]));
                float sum = __expf(a[j][0]-m)+__expf(a[j][1]-m)
                          + __expf(a[j][2]-m)+__expf(a[j][3]-m);
                float lse = m + __logf(sum);
                int c = ci[j];
                float xc = (c==0) ? a[j][0] : ((c==1) ? a[j][1] : ((c==2) ? a[j][2] : a[j][3]));
                s += lse - xc;
            }
        }

        const float4* gp = (const float4*)(geo + (size_t)b*16*HW + q);
        const float4* dp = (const float4*)(gd  + (size_t)b*9 *HW + q);
        const float4* gp2= (const float4*)(gg  + (size_t)b*3 *HW + q);
        const float4* rp = (const float4*)(gr  + (size_t)b*4 *HW + q);
        float t9 = 0, t3 = 0, t4v = 0;
        #pragma unroll
        for (int i = 0; i < 9; i++) {
            float4 a = __ldcs(gp + (size_t)i*(HW/4));
            float4 c = __ldcs(dp + (size_t)i*(HW/4));
            t9 += fabsf(a.x-c.x)+fabsf(a.y-c.y)+fabsf(a.z-c.z)+fabsf(a.w-c.w);
        }
        #pragma unroll
        for (int i = 0; i < 3; i++) {
            float4 a = __ldcs(gp + (size_t)(9+i)*(HW/4));
            float4 c = __ldcs(gp2 + (size_t)i*(HW/4));
            t3 += fabsf(a.x-c.x)+fabsf(a.y-c.y)+fabsf(a.z-c.z)+fabsf(a.w-c.w);
        }
        #pragma unroll
        for (int i = 0; i < 4; i++) {
            float4 a = __ldcs(gp + (size_t)(12+i)*(HW/4));
            float4 c = __ldcs(rp + (size_t)i*(HW/4));
            t4v += fabsf(a.x-c.x)+fabsf(a.y-c.y)+fabsf(a.z-c.z)+fabsf(a.w-c.w);
        }

        __shared__ float sh[4][8];
        int lane = threadIdx.x & 31, wid = threadIdx.x >> 5;
        float v0 = warp_redf(s);
        float v1 = warp_redf(t9);
        float v2 = warp_redf(t3);
        float v3 = warp_redf(t4v);
        if (lane == 0) { sh[0][wid]=v0; sh[1][wid]=v1; sh[2][wid]=v2; sh[3][wid]=v3; }
        __syncthreads();
        if (wid == 0) {
            v0 = lane < 8 ? sh[0][lane] : 0.f;
            v1 = lane < 8 ? sh[1][lane] : 0.f;
            v2 = lane < 8 ? sh[2][lane] : 0.f;
            v3 = lane < 8 ? sh[3][lane] : 0.f;
            v0 = warp_redf(v0); v1 = warp_redf(v1); v2 = warp_redf(v2); v3 = warp_redf(v3);
            if (lane == 0) {
                atomicAdd(&g_s.sem, (double)v0); atomicAdd(&g_s.a9, (double)v1);
                atomicAdd(&g_s.a3, (double)v2);  atomicAdd(&g_s.a4, (double)v3);
            }
        }
    } else {
        // ---------------- segment sums (bitmask boundary) --------------------
        int bid = blockIdx.x - SEM_BLOCKS;
        int b   = bid / SEG_BLK_PER_IMG;
        int blk = bid - b*SEG_BLK_PER_IMG;

        __shared__ float s_cnt[NINST], s_ws[NINST], s_ew[NINST*EDIM];
        for (int i = threadIdx.x; i < NINST; i += blockDim.x) { s_cnt[i]=0.f; s_ws[i]=0.f; }
        for (int i = threadIdx.x; i < NINST*EDIM; i += blockDim.x) s_ew[i]=0.f;
        __syncthreads();

        const int*   L = lbl + b*HW;
        const float* E = emb + (size_t)b*EDIM*HW;

        int r = blk*blockDim.x + threadIdx.x;     // one 16-run per thread
        int y  = r / RUNS_X;
        int x0 = (r - y*RUNS_X) * 16;
        int base = y*Wn + x0;

        const int*  rM = L + base;
        const int4* m4 = (const int4*)rM;
        int4 a0 = m4[0], a1 = m4[1], a2 = m4[2], a3 = m4[3];
        int l = a0.x;
        bool uni = (a0.y==l)&(a0.z==l)&(a0.w==l)
                 & (a1.x==l)&(a1.y==l)&(a1.z==l)&(a1.w==l)
                 & (a2.x==l)&(a2.y==l)&(a2.z==l)&(a2.w==l)
                 & (a3.x==l)&(a3.y==l)&(a3.z==l)&(a3.w==l);

        if (uni) {
            int ym = y > 0 ? y-1 : 0, yp = y < Hn-1 ? y+1 : Hn-1;
            const int* rT = L + ym*Wn + x0;
            const int* rB = L + yp*Wn + x0;
            const int4* t4 = (const int4*)rT;
            const int4* b4 = (const int4*)rB;
            unsigned int bad = 0;
            #pragma unroll
            for (int k = 0; k < 4; k++) {
                int4 tt = t4[k];
                bad |= ((unsigned)(tt.x!=l)<<(1+4*k)) | ((unsigned)(tt.y!=l)<<(2+4*k))
                     | ((unsigned)(tt.z!=l)<<(3+4*k)) | ((unsigned)(tt.w!=l)<<(4+4*k));
                int4 bb = b4[k];
                bad |= ((unsigned)(bb.x!=l)<<(1+4*k)) | ((unsigned)(bb.y!=l)<<(2+4*k))
                     | ((unsigned)(bb.z!=l)<<(3+4*k)) | ((unsigned)(bb.w!=l)<<(4+4*k));
            }
            int xl = (x0 > 0) ? -1 : 0;
            int xr = (x0+16 < Wn) ? 16 : 15;
            bad |= (unsigned)(rT[xl]!=l) | ((unsigned)(rT[xr]!=l)<<17);
            bad |= (unsigned)(rB[xl]!=l) | ((unsigned)(rB[xr]!=l)<<17);
            bad |= (unsigned)(rM[xl]!=l) | ((unsigned)(rM[xr]!=l)<<17);

            unsigned int mask = (bad | (bad>>1) | (bad>>2)) & 0xFFFFu;

            float wv[16];
            #pragma unroll
            for (int i = 0; i < 16; i++) wv[i] = ((mask>>i)&1u) ? 10.0f : 1.0f;

            atomicAdd(&s_cnt[l], 16.0f);
            atomicAdd(&s_ws [l], 16.0f + 9.0f*(float)__popc(mask));
            #pragma unroll
            for (int c = 0; c < EDIM; c++) {
                const float4* Ep = (const float4*)(E + (size_t)c*HW + base);
                float4 e0 = Ep[0], e1 = Ep[1], e2 = Ep[2], e3 = Ep[3];
                float acc = e0.x*wv[0]+e0.y*wv[1]+e0.z*wv[2]+e0.w*wv[3]
                          + e1.x*wv[4]+e1.y*wv[5]+e1.z*wv[6]+e1.w*wv[7]
                          + e2.x*wv[8]+e2.y*wv[9]+e2.z*wv[10]+e2.w*wv[11]
                          + e3.x*wv[12]+e3.y*wv[13]+e3.z*wv[14]+e3.w*wv[15];
                atomicAdd(&s_ew[l*EDIM+c], acc);
            }
            g_runinfo[b*RUNS_PER_IMG + r] = mask | ((unsigned)l<<16) | (1u<<31);
        } else {
            int ls[16] = {a0.x,a0.y,a0.z,a0.w, a1.x,a1.y,a1.z,a1.w,
                          a2.x,a2.y,a2.z,a2.w, a3.x,a3.y,a3.z,a3.w};
            unsigned int mask = 0;
            #pragma unroll 1
            for (int i = 0; i < 16; i++) {
                int li = ls[i];
                float w = bweight(L, y, x0+i, li);
                if (w > 1.f) mask |= (1u<<i);
                atomicAdd(&s_cnt[li], 1.0f);
                atomicAdd(&s_ws [li], w);
                for (int c = 0; c < EDIM; c++)
                    atomicAdd(&s_ew[li*EDIM+c], E[(size_t)c*HW + base + i] * w);
            }
            g_runinfo[b*RUNS_PER_IMG + r] = mask;   // uni bit = 0
        }
        __syncthreads();
        for (int i = threadIdx.x; i < NINST; i += blockDim.x) {
            if (s_cnt[i] != 0.f) atomicAdd(&g_s.cnt[b*NINST+i], s_cnt[i]);
            if (s_ws [i] != 0.f) atomicAdd(&g_s.ws [b*NINST+i], s_ws [i]);
        }
        for (int i = threadIdx.x; i < NINST*EDIM; i += blockDim.x)
            if (s_ew[i] != 0.f) atomicAdd(&g_s.ew[b*NINST*EDIM+i], s_ew[i]);
    }
}

// ======== K2: pull term — 8 px/thread, run metadata cached ====================
__global__ void __launch_bounds__(256)
K2(const int* __restrict__ lbl, const float* __restrict__ emb)
{
    int b   = blockIdx.x / K2_BLK_PER_IMG;
    int blk = blockIdx.x - b*K2_BLK_PER_IMG;

    __shared__ float s_ctr[NINST*EDIM];
    __shared__ float s_pull[NINST];
    for (int i = threadIdx.x; i < NINST*EDIM; i += blockDim.x)
        s_ctr[i] = g_s.ew[b*NINST*EDIM + i] / (g_s.ws[b*NINST + (i>>3)] + 1e-8f);
    for (int i = threadIdx.x; i < NINST; i += blockDim.x) s_pull[i] = 0.f;
    __syncthreads();

    const float* E = emb + (size_t)b*EDIM*HW;

    int r8 = blk*blockDim.x + threadIdx.x;    // half-run (8 px)
    int y  = r8 / (2*RUNS_X);
    int x8 = (r8 - y*(2*RUNS_X)) * 8;
    int base = y*Wn + x8;

    unsigned int info = g_runinfo[b*RUNS_PER_IMG + y*RUNS_X + (x8>>4)];
    unsigned int mask8 = (info >> (((x8>>3)&1)*8)) & 0xFFu;

    if (info & (1u<<31)) {
        int l = (int)((info>>16) & 0x3Fu);
        float ss[8];
        #pragma unroll
        for (int i = 0; i < 8; i++) ss[i] = 0.f;
        #pragma unroll
        for (int c = 0; c < EDIM; c++) {
            float cc = s_ctr[l*EDIM+c];
            const float4* Ep = (const float4*)(E + (size_t)c*HW + base);
            float4 e0 = Ep[0], e1 = Ep[1];
            float d0=e0.x-cc, d1=e0.y-cc, d2=e0.z-cc, d3=e0.w-cc;
            float d4=e1.x-cc, d5=e1.y-cc, d6=e1.z-cc, d7=e1.w-cc;
            ss[0]+=d0*d0; ss[1]+=d1*d1; ss[2]+=d2*d2; ss[3]+=d3*d3;
            ss[4]+=d4*d4; ss[5]+=d5*d5; ss[6]+=d6*d6; ss[7]+=d7*d7;
        }
        float acc = 0.f;
        #pragma unroll
        for (int i = 0; i < 8; i++) {
            float dist = sqrtf(fmaxf(ss[i], 1e-12f));
            float t = fmaxf(dist - 0.5f, 0.f);
            float w = ((mask8>>i)&1u) ? 10.0f : 1.0f;
            acc += t*t*w;
        }
        atomicAdd(&s_pull[l], acc);
    } else {
        const int* Lp = lbl + b*HW + base;
        int4 L0 = ((const int4*)Lp)[0];
        int4 L1 = ((const int4*)Lp)[1];
        int ls[8] = {L0.x,L0.y,L0.z,L0.w, L1.x,L1.y,L1.z,L1.w};
        #pragma unroll 1
        for (int i = 0; i < 8; i++) {
            int l = ls[i];
            float ssv = 0.f;
            for (int c = 0; c < EDIM; c++) {
                float d = E[(size_t)c*HW + base + i] - s_ctr[l*EDIM+c];
                ssv += d*d;
            }
            float dist = sqrtf(fmaxf(ssv, 1e-12f));
            float t = fmaxf(dist - 0.5f, 0.f);
            float w = ((mask8>>i)&1u) ? 10.0f : 1.0f;
            atomicAdd(&s_pull[l], t*t*w);
        }
    }
    __syncthreads();
    for (int i = threadIdx.x; i < NINST; i += blockDim.x)
        if (s_pull[i] != 0.f) atomicAdd(&g_s.pull[b*NINST+i], s_pull[i]);
}

// ======== K3: finalize ========================================================
__global__ void __launch_bounds__(256)
K3(float* __restrict__ out, int out_size)
{
    __shared__ float s_ctr[Bn][NINST*EDIM];
    __shared__ float s_cnt[Bn][NINST];
    __shared__ float rp[Bn], rq[Bn], rn[Bn];
    __shared__ int   rpres[Bn];

    for (int i = threadIdx.x; i < Bn*NINST*EDIM; i += blockDim.x) {
        int b = i / (NINST*EDIM), k = i % (NINST*EDIM);
        s_ctr[b][k] = g_s.ew[i] / (g_s.ws[b*NINST + (k>>3)] + 1e-8f);
    }
    for (int i = threadIdx.x; i < Bn*NINST; i += blockDim.x)
        s_cnt[i/NINST][i%NINST] = g_s.cnt[i];
    __syncthreads();

    int wid = threadIdx.x >> 5, lane = threadIdx.x & 31;
    if (wid < Bn) {
        int b = wid;
        float pull = 0, norm = 0; int np = 0;
        for (int k = lane; k < NINST; k += 32) {
            bool pres = (k > 0) && (s_cnt[b][k] > 0.f);
            if (pres) {
                pull += g_s.pull[b*NINST+k] / fmaxf(s_cnt[b][k], 1.0f);
                float ssn = 0;
                #pragma unroll
                for (int c = 0; c < EDIM; c++) { float v = s_ctr[b][k*EDIM+c]; ssn += v*v; }
                norm += sqrtf(fmaxf(ssn, 1e-12f));
                np++;
            }
        }
        float push = 0; int npair = 0;
        for (int idx = lane; idx < NINST*NINST; idx += 32) {
            int i = idx / NINST, j = idx % NINST;
            if (j > i && i > 0 && s_cnt[b][i] > 0.f && s_cnt[b][j] > 0.f) {
                float ssd = 0;
                #pragma unroll
                for (int c = 0; c < EDIM; c++) {
                    float d = s_ctr[b][i*EDIM+c] - s_ctr[b][j*EDIM+c];
                    ssd += d*d;
                }
                float pd = sqrtf(fmaxf(ssd, 1e-12f));
                float t = fmaxf(3.0f - pd, 0.f);
                push += t*t; npair++;
            }
        }
        pull = warp_redf(pull); norm = warp_redf(norm); push = warp_redf(push);
        np   = __reduce_add_sync(0xffffffffu, np);
        npair= __reduce_add_sync(0xffffffffu, npair);
        if (lane == 0) {
            rp[b] = pull;
            rq[b] = push / fmaxf((float)npair, 1.0f);
            rn[b] = norm / fmaxf((float)np, 1.0f);
            rpres[b] = (np > 0) ? 1 : 0;
        }
    }
    __syncthreads();
    if (threadIdx.x == 0) {
        float pull = 0, push = 0, norm = 0; int n = 0;
        for (int bb = 0; bb < Bn; bb++) { pull += rp[bb]; push += rq[bb]; norm += rn[bb]; n += rpres[bb]; }
        float nn  = fmaxf((float)n, 1.0f);
        float ins = (pull + push + 0.001f*norm) / nn;
        float semv = (float)(g_s.sem / (double)NPIX);
        float aff  = (float)(g_s.a9/(double)((size_t)Bn*9*HW)
                           + g_s.a3/(double)((size_t)Bn*3*HW)
                           + g_s.a4/(double)((size_t)Bn*4*HW));
        out[0] = semv + aff + ins;
        if (out_size > 1) out[1] = semv;
        if (out_size > 2) out[2] = aff;
        if (out_size > 3) out[3] = ins;
    }
}

// ---------------- entry -------------------------------------------------------
extern "C" void kernel_launch(void* const* d_in, const int* in_sizes, int n_in,
                              void* d_out, int out_size)
{
    const float* sem  = (const float*)d_in[0];
    const int*   cl   = (const int*)  d_in[1];
    const float* inst = (const float*)d_in[2];
    const float* geo  = (const float*)d_in[3];
    const float* gd   = (const float*)d_in[4];
    const float* gg   = (const float*)d_in[5];
    const float* gr   = (const float*)d_in[6];
    const int*   lbl  = (const int*)  d_in[7];
    float* out = (float*)d_out;

    void* scr = nullptr;
    cudaGetSymbolAddress(&scr, g_s);
    cudaMemsetAsync(scr, 0, sizeof(Scr));

    K1<<<SEM_BLOCKS + SEG_BLOCKS, 256>>>(sem, cl, geo, gd, gg, gr, lbl, inst);
    K2<<<K2_BLOCKS, 256>>>(lbl, inst);
    K3<<<1, 256>>>(out, out_size);
}

// round 4
// speedup vs baseline: 4.0929x; 1.3090x over previous
#include <cuda_runtime.h>
#include <cuda_bf16.h>
#include <math.h>

#define Bn    8
#define Hn    384
#define Wn    384
#define HW    (Hn*Wn)
#define NPIX  (Bn*HW)
#define NCLS  4
#define EDIM  8
#define NINST 33
#define RUNS_PER_IMG (HW/16)          // 9216
#define RUNS_X       (Wn/16)          // 24
#define SEG_BLK_PER_IMG 36
#define SEG_BLOCKS   (SEG_BLK_PER_IMG*Bn)       // 288
#define SEM_BLOCKS   (NPIX/4/256)               // 1152
#define HR_PER_IMG   (RUNS_PER_IMG*2)           // 18432 half-runs
#define K2_BLK_PER_IMG (HR_PER_IMG/256)         // 72
#define K2_BLOCKS    (K2_BLK_PER_IMG*Bn)        // 576
#define TOTAL_BLOCKS (SEG_BLOCKS + SEM_BLOCKS + K2_BLOCKS + 1)

// ---------------- scratch ----------------------------------------------------
struct Scr {
    double sem, a9, a3, a4;
    float  cnt [Bn*NINST];
    float  ws  [Bn*NINST];
    float  ew  [Bn*NINST*EDIM];
    float  pull[Bn*NINST];
    int    done_seg, done_sem, done_k2;
};
__device__ Scr g_s;
__device__ unsigned int g_runinfo[Bn*RUNS_PER_IMG];   // mask16 | label<<16 | uni<<31

__device__ __forceinline__ float warp_redf(float v){
    #pragma unroll
    for (int o = 16; o > 0; o >>= 1) v += __shfl_down_sync(0xffffffffu, v, o);
    return v;
}

// per-pixel boundary weight (fallback only)
__device__ __forceinline__ float bweight(const int* __restrict__ L, int y, int x, int l)
{
    int ym = y > 0 ? y-1 : 0, yp = y < Hn-1 ? y+1 : Hn-1;
    int xm = x > 0 ? x-1 : 0, xp = x < Wn-1 ? x+1 : Wn-1;
    const int* r0 = L + ym*Wn;
    const int* r1 = L + y *Wn;
    const int* r2 = L + yp*Wn;
    bool bd = (r0[xm]!=l) | (r0[x]!=l) | (r0[xp]!=l)
            | (r1[xm]!=l) |              (r1[xp]!=l)
            | (r2[xm]!=l) | (r2[x]!=l) | (r2[xp]!=l);
    return bd ? 10.0f : 1.0f;
}

__device__ __forceinline__ void spin_until(int* ctr, int target)
{
    __shared__ int ok;
    if (threadIdx.x == 0) {
        while (atomicAdd(ctr, 0) < target) __nanosleep(64);
        __threadfence();
        ok = 1;
    }
    __syncthreads();
}

__device__ __forceinline__ void signal_done(int* ctr)
{
    __syncthreads();
    if (threadIdx.x == 0) { __threadfence(); atomicAdd(ctr, 1); }
}

// =============================================================================
// One persistent kernel. Block roles by blockIdx.x:
//   [0, SEG)                 : segment sums (cnt / w_sum / weighted embed)
//   [SEG, SEG+SEM)           : semantic NLL + affinity L1
//   [SEG+SEM, SEG+SEM+K2B)   : pull term (spin-waits on seg counter)
//   last                     : finalize   (spin-waits on sem + pull counters)
// =============================================================================
__global__ void __launch_bounds__(256, 5)
K(const float* __restrict__ sem, const int* __restrict__ cl,
  const float* __restrict__ geo, const float* __restrict__ gd,
  const float* __restrict__ gg,  const float* __restrict__ gr,
  const int*   __restrict__ lbl, const float* __restrict__ emb,
  float* __restrict__ out, int out_size)
{
    int bid = blockIdx.x;

    // ======================= SEG =============================================
    if (bid < SEG_BLOCKS) {
        int b   = bid / SEG_BLK_PER_IMG;
        int blk = bid - b*SEG_BLK_PER_IMG;

        __shared__ float s_cnt[NINST], s_ws[NINST], s_ew[NINST*EDIM];
        for (int i = threadIdx.x; i < NINST; i += blockDim.x) { s_cnt[i]=0.f; s_ws[i]=0.f; }
        for (int i = threadIdx.x; i < NINST*EDIM; i += blockDim.x) s_ew[i]=0.f;
        __syncthreads();

        const int*   L = lbl + b*HW;
        const float* E = emb + (size_t)b*EDIM*HW;

        int r = blk*blockDim.x + threadIdx.x;
        int y  = r / RUNS_X;
        int x0 = (r - y*RUNS_X) * 16;
        int base = y*Wn + x0;

        const int*  rM = L + base;
        const int4* m4 = (const int4*)rM;
        int4 a0 = m4[0], a1 = m4[1], a2 = m4[2], a3 = m4[3];
        int l = a0.x;
        bool uni = (a0.y==l)&(a0.z==l)&(a0.w==l)
                 & (a1.x==l)&(a1.y==l)&(a1.z==l)&(a1.w==l)
                 & (a2.x==l)&(a2.y==l)&(a2.z==l)&(a2.w==l)
                 & (a3.x==l)&(a3.y==l)&(a3.z==l)&(a3.w==l);

        if (uni) {
            int ym = y > 0 ? y-1 : 0, yp = y < Hn-1 ? y+1 : Hn-1;
            const int* rT = L + ym*Wn + x0;
            const int* rB = L + yp*Wn + x0;
            const int4* t4 = (const int4*)rT;
            const int4* b4 = (const int4*)rB;
            unsigned int bad = 0;
            #pragma unroll
            for (int k = 0; k < 4; k++) {
                int4 tt = t4[k];
                bad |= ((unsigned)(tt.x!=l)<<(1+4*k)) | ((unsigned)(tt.y!=l)<<(2+4*k))
                     | ((unsigned)(tt.z!=l)<<(3+4*k)) | ((unsigned)(tt.w!=l)<<(4+4*k));
                int4 bb = b4[k];
                bad |= ((unsigned)(bb.x!=l)<<(1+4*k)) | ((unsigned)(bb.y!=l)<<(2+4*k))
                     | ((unsigned)(bb.z!=l)<<(3+4*k)) | ((unsigned)(bb.w!=l)<<(4+4*k));
            }
            int xl = (x0 > 0) ? -1 : 0;
            int xr = (x0+16 < Wn) ? 16 : 15;
            bad |= (unsigned)(rT[xl]!=l) | ((unsigned)(rT[xr]!=l)<<17);
            bad |= (unsigned)(rB[xl]!=l) | ((unsigned)(rB[xr]!=l)<<17);
            bad |= (unsigned)(rM[xl]!=l) | ((unsigned)(rM[xr]!=l)<<17);

            unsigned int mask = (bad | (bad>>1) | (bad>>2)) & 0xFFFFu;

            atomicAdd(&s_cnt[l], 16.0f);
            atomicAdd(&s_ws [l], 16.0f + 9.0f*(float)__popc(mask));
            #pragma unroll
            for (int c = 0; c < EDIM; c++) {
                const float4* Ep = (const float4*)(E + (size_t)c*HW + base);
                float4 e0 = Ep[0], e1 = Ep[1], e2 = Ep[2], e3 = Ep[3];
                // acc = sum(e_i * (1 + 9*mask_i))
                float acc = 0.f;
                float ev[16] = {e0.x,e0.y,e0.z,e0.w, e1.x,e1.y,e1.z,e1.w,
                                e2.x,e2.y,e2.z,e2.w, e3.x,e3.y,e3.z,e3.w};
                #pragma unroll
                for (int i = 0; i < 16; i++)
                    acc += ev[i] * fmaf((float)((mask>>i)&1u), 9.0f, 1.0f);
                atomicAdd(&s_ew[l*EDIM+c], acc);
            }
            g_runinfo[b*RUNS_PER_IMG + r] = mask | ((unsigned)l<<16) | (1u<<31);
        } else {
            int ls[16] = {a0.x,a0.y,a0.z,a0.w, a1.x,a1.y,a1.z,a1.w,
                          a2.x,a2.y,a2.z,a2.w, a3.x,a3.y,a3.z,a3.w};
            unsigned int mask = 0;
            #pragma unroll 1
            for (int i = 0; i < 16; i++) {
                int li = ls[i];
                float w = bweight(L, y, x0+i, li);
                if (w > 1.f) mask |= (1u<<i);
                atomicAdd(&s_cnt[li], 1.0f);
                atomicAdd(&s_ws [li], w);
                for (int c = 0; c < EDIM; c++)
                    atomicAdd(&s_ew[li*EDIM+c], E[(size_t)c*HW + base + i] * w);
            }
            g_runinfo[b*RUNS_PER_IMG + r] = mask;
        }
        __syncthreads();
        for (int i = threadIdx.x; i < NINST; i += blockDim.x) {
            if (s_cnt[i] != 0.f) atomicAdd(&g_s.cnt[b*NINST+i], s_cnt[i]);
            if (s_ws [i] != 0.f) atomicAdd(&g_s.ws [b*NINST+i], s_ws [i]);
        }
        for (int i = threadIdx.x; i < NINST*EDIM; i += blockDim.x)
            if (s_ew[i] != 0.f) atomicAdd(&g_s.ew[b*NINST*EDIM+i], s_ew[i]);

        signal_done(&g_s.done_seg);
        return;
    }
    bid -= SEG_BLOCKS;

    // ======================= SEMAFF ==========================================
    if (bid < SEM_BLOCKS) {
        int t  = bid*blockDim.x + threadIdx.x;
        int H4 = HW/4;
        int b  = t / H4;
        int q4 = t - b*H4;
        size_t q = (size_t)q4 * 4;

        const float4* s4 = (const float4*)(sem + (size_t)b*NCLS*HW + q);
        float4 x0 = __ldcs(s4);
        float4 x1 = __ldcs(s4 + HW/4);
        float4 x2 = __ldcs(s4 + 2*(HW/4));
        float4 x3 = __ldcs(s4 + 3*(HW/4));
        int4 cc = __ldcs((const int4*)(cl + (size_t)b*HW + q));

        float s = 0.f;
        {
            float a[4][4] = {{x0.x,x1.x,x2.x,x3.x},{x0.y,x1.y,x2.y,x3.y},
                             {x0.z,x1.z,x2.z,x3.z},{x0.w,x1.w,x2.w,x3.w}};
            int   ci[4] = {cc.x, cc.y, cc.z, cc.w};
            #pragma unroll
            for (int j = 0; j < 4; j++) {
                float m = fmaxf(fmaxf(a[j][0],a[j][1]), fmaxf(a[j][2],a[j][3]));
                float sum = __expf(a[j][0]-m)+__expf(a[j][1]-m)
                          + __expf(a[j][2]-m)+__expf(a[j][3]-m);
                float lse = m + __logf(sum);
                int c = ci[j];
                float xc = (c==0) ? a[j][0] : ((c==1) ? a[j][1] : ((c==2) ? a[j][2] : a[j][3]));
                s += lse - xc;
            }
        }

        const float4* gp = (const float4*)(geo + (size_t)b*16*HW + q);
        const float4* dp = (const float4*)(gd  + (size_t)b*9 *HW + q);
        const float4* gp2= (const float4*)(gg  + (size_t)b*3 *HW + q);
        const float4* rp = (const float4*)(gr  + (size_t)b*4 *HW + q);
        float t9 = 0, t3 = 0, t4v = 0;
        #pragma unroll
        for (int i = 0; i < 9; i++) {
            float4 a = __ldcs(gp + (size_t)i*(HW/4));
            float4 c = __ldcs(dp + (size_t)i*(HW/4));
            t9 += fabsf(a.x-c.x)+fabsf(a.y-c.y)+fabsf(a.z-c.z)+fabsf(a.w-c.w);
        }
        #pragma unroll
        for (int i = 0; i < 3; i++) {
            float4 a = __ldcs(gp + (size_t)(9+i)*(HW/4));
            float4 c = __ldcs(gp2 + (size_t)i*(HW/4));
            t3 += fabsf(a.x-c.x)+fabsf(a.y-c.y)+fabsf(a.z-c.z)+fabsf(a.w-c.w);
        }
        #pragma unroll
        for (int i = 0; i < 4; i++) {
            float4 a = __ldcs(gp + (size_t)(12+i)*(HW/4));
            float4 c = __ldcs(rp + (size_t)i*(HW/4));
            t4v += fabsf(a.x-c.x)+fabsf(a.y-c.y)+fabsf(a.z-c.z)+fabsf(a.w-c.w);
        }

        __shared__ float sh[4][8];
        int lane = threadIdx.x & 31, wid = threadIdx.x >> 5;
        float v0 = warp_redf(s);
        float v1 = warp_redf(t9);
        float v2 = warp_redf(t3);
        float v3 = warp_redf(t4v);
        if (lane == 0) { sh[0][wid]=v0; sh[1][wid]=v1; sh[2][wid]=v2; sh[3][wid]=v3; }
        __syncthreads();
        if (wid == 0) {
            v0 = lane < 8 ? sh[0][lane] : 0.f;
            v1 = lane < 8 ? sh[1][lane] : 0.f;
            v2 = lane < 8 ? sh[2][lane] : 0.f;
            v3 = lane < 8 ? sh[3][lane] : 0.f;
            v0 = warp_redf(v0); v1 = warp_redf(v1); v2 = warp_redf(v2); v3 = warp_redf(v3);
            if (lane == 0) {
                atomicAdd(&g_s.sem, (double)v0); atomicAdd(&g_s.a9, (double)v1);
                atomicAdd(&g_s.a3, (double)v2);  atomicAdd(&g_s.a4, (double)v3);
            }
        }
        signal_done(&g_s.done_sem);
        return;
    }
    bid -= SEM_BLOCKS;

    // ======================= PULL (waits on seg) =============================
    if (bid < K2_BLOCKS) {
        spin_until(&g_s.done_seg, SEG_BLOCKS);

        int b   = bid / K2_BLK_PER_IMG;
        int blk = bid - b*K2_BLK_PER_IMG;

        __shared__ float s_ctr[NINST*EDIM];
        __shared__ float s_pull[NINST];
        for (int i = threadIdx.x; i < NINST*EDIM; i += blockDim.x)
            s_ctr[i] = g_s.ew[b*NINST*EDIM + i] / (g_s.ws[b*NINST + (i>>3)] + 1e-8f);
        for (int i = threadIdx.x; i < NINST; i += blockDim.x) s_pull[i] = 0.f;
        __syncthreads();

        const float* E = emb + (size_t)b*EDIM*HW;

        int r8 = blk*blockDim.x + threadIdx.x;
        int y  = r8 / (2*RUNS_X);
        int x8 = (r8 - y*(2*RUNS_X)) * 8;
        int base = y*Wn + x8;

        unsigned int info = g_runinfo[b*RUNS_PER_IMG + y*RUNS_X + (x8>>4)];
        unsigned int mask8 = (info >> (((x8>>3)&1)*8)) & 0xFFu;

        if (info & (1u<<31)) {
            int l = (int)((info>>16) & 0x3Fu);
            float ss[8];
            #pragma unroll
            for (int i = 0; i < 8; i++) ss[i] = 0.f;
            #pragma unroll
            for (int c = 0; c < EDIM; c++) {
                float ccv = s_ctr[l*EDIM+c];
                const float4* Ep = (const float4*)(E + (size_t)c*HW + base);
                float4 e0 = Ep[0], e1 = Ep[1];
                float d0=e0.x-ccv, d1=e0.y-ccv, d2=e0.z-ccv, d3=e0.w-ccv;
                float d4=e1.x-ccv, d5=e1.y-ccv, d6=e1.z-ccv, d7=e1.w-ccv;
                ss[0]+=d0*d0; ss[1]+=d1*d1; ss[2]+=d2*d2; ss[3]+=d3*d3;
                ss[4]+=d4*d4; ss[5]+=d5*d5; ss[6]+=d6*d6; ss[7]+=d7*d7;
            }
            float acc = 0.f;
            #pragma unroll
            for (int i = 0; i < 8; i++) {
                float dist = sqrtf(fmaxf(ss[i], 1e-12f));
                float t = fmaxf(dist - 0.5f, 0.f);
                float w = fmaf((float)((mask8>>i)&1u), 9.0f, 1.0f);
                acc += t*t*w;
            }
            atomicAdd(&s_pull[l], acc);
        } else {
            const int* Lp = lbl + b*HW + base;
            int4 L0 = ((const int4*)Lp)[0];
            int4 L1 = ((const int4*)Lp)[1];
            int ls[8] = {L0.x,L0.y,L0.z,L0.w, L1.x,L1.y,L1.z,L1.w};
            #pragma unroll 1
            for (int i = 0; i < 8; i++) {
                int l = ls[i];
                float ssv = 0.f;
                for (int c = 0; c < EDIM; c++) {
                    float d = E[(size_t)c*HW + base + i] - s_ctr[l*EDIM+c];
                    ssv += d*d;
                }
                float dist = sqrtf(fmaxf(ssv, 1e-12f));
                float t = fmaxf(dist - 0.5f, 0.f);
                float w = fmaf((float)((mask8>>i)&1u), 9.0f, 1.0f);
                atomicAdd(&s_pull[l], t*t*w);
            }
        }
        __syncthreads();
        for (int i = threadIdx.x; i < NINST; i += blockDim.x)
            if (s_pull[i] != 0.f) atomicAdd(&g_s.pull[b*NINST+i], s_pull[i]);

        signal_done(&g_s.done_k2);
        return;
    }

    // ======================= FINALIZE ========================================
    spin_until(&g_s.done_sem, SEM_BLOCKS);
    spin_until(&g_s.done_k2,  K2_BLOCKS);

    __shared__ float s_ctr[Bn][NINST*EDIM];
    __shared__ float s_cnt[Bn][NINST];
    __shared__ float rp[Bn], rq[Bn], rn[Bn];
    __shared__ int   rpres[Bn];

    for (int i = threadIdx.x; i < Bn*NINST*EDIM; i += blockDim.x) {
        int b = i / (NINST*EDIM), k = i % (NINST*EDIM);
        s_ctr[b][k] = g_s.ew[i] / (g_s.ws[b*NINST + (k>>3)] + 1e-8f);
    }
    for (int i = threadIdx.x; i < Bn*NINST; i += blockDim.x)
        s_cnt[i/NINST][i%NINST] = g_s.cnt[i];
    __syncthreads();

    int wid = threadIdx.x >> 5, lane = threadIdx.x & 31;
    if (wid < Bn) {
        int b = wid;
        float pull = 0, norm = 0; int np = 0;
        for (int k = lane; k < NINST; k += 32) {
            bool pres = (k > 0) && (s_cnt[b][k] > 0.f);
            if (pres) {
                pull += g_s.pull[b*NINST+k] / fmaxf(s_cnt[b][k], 1.0f);
                float ssn = 0;
                #pragma unroll
                for (int c = 0; c < EDIM; c++) { float v = s_ctr[b][k*EDIM+c]; ssn += v*v; }
                norm += sqrtf(fmaxf(ssn, 1e-12f));
                np++;
            }
        }
        float push = 0; int npair = 0;
        for (int idx = lane; idx < NINST*NINST; idx += 32) {
            int i = idx / NINST, j = idx % NINST;
            if (j > i && i > 0 && s_cnt[b][i] > 0.f && s_cnt[b][j] > 0.f) {
                float ssd = 0;
                #pragma unroll
                for (int c = 0; c < EDIM; c++) {
                    float d = s_ctr[b][i*EDIM+c] - s_ctr[b][j*EDIM+c];
                    ssd += d*d;
                }
                float pd = sqrtf(fmaxf(ssd, 1e-12f));
                float t = fmaxf(3.0f - pd, 0.f);
                push += t*t; npair++;
            }
        }
        pull = warp_redf(pull); norm = warp_redf(norm); push = warp_redf(push);
        np   = __reduce_add_sync(0xffffffffu, np);
        npair= __reduce_add_sync(0xffffffffu, npair);
        if (lane == 0) {
            rp[b] = pull;
            rq[b] = push / fmaxf((float)npair, 1.0f);
            rn[b] = norm / fmaxf((float)np, 1.0f);
            rpres[b] = (np > 0) ? 1 : 0;
        }
    }
    __syncthreads();
    if (threadIdx.x == 0) {
        float pull = 0, push = 0, norm = 0; int n = 0;
        for (int bb = 0; bb < Bn; bb++) { pull += rp[bb]; push += rq[bb]; norm += rn[bb]; n += rpres[bb]; }
        float nn  = fmaxf((float)n, 1.0f);
        float ins = (pull + push + 0.001f*norm) / nn;
        float semv = (float)(g_s.sem / (double)NPIX);
        float aff  = (float)(g_s.a9/(double)((size_t)Bn*9*HW)
                           + g_s.a3/(double)((size_t)Bn*3*HW)
                           + g_s.a4/(double)((size_t)Bn*4*HW));
        out[0] = semv + aff + ins;
        if (out_size > 1) out[1] = semv;
        if (out_size > 2) out[2] = aff;
        if (out_size > 3) out[3] = ins;
    }
}

// ---------------- entry -------------------------------------------------------
extern "C" void kernel_launch(void* const* d_in, const int* in_sizes, int n_in,
                              void* d_out, int out_size)
{
    const float* sem  = (const float*)d_in[0];
    const int*   cl   = (const int*)  d_in[1];
    const float* inst = (const float*)d_in[2];
    const float* geo  = (const float*)d_in[3];
    const float* gd   = (const float*)d_in[4];
    const float* gg   = (const float*)d_in[5];
    const float* gr   = (const float*)d_in[6];
    const int*   lbl  = (const int*)  d_in[7];
    float* out = (float*)d_out;

    void* scr = nullptr;
    cudaGetSymbolAddress(&scr, g_s);
    cudaMemsetAsync(scr, 0, sizeof(Scr));

    K<<<TOTAL_BLOCKS, 256>>>(sem, cl, geo, gd, gg, gr, lbl, inst, out, out_size);
}